// round 11
// baseline (speedup 1.0000x reference)
#include <cuda_runtime.h>
#include <math.h>

#define D 128
#define MAXN 100000
#define MAXE 1600000
#define BM 64
#define KC 32

// ---------------- scratch (static device globals; 16B-aligned for float4) -----
__device__ __align__(16) float g_agg[(size_t)MAXN * D];  // aggregated MEAN feats
__device__ __align__(16) float g_h[(size_t)MAXN * D];    // pre-BN hidden
__device__ __align__(16) float g_colacc[2 * D];          // col sum | col sumsq
__device__ __align__(16) float g_ab[2 * D];              // bn scale | bn shift
__device__ int g_deg[MAXN];
__device__ int g_off[MAXN + 1];
__device__ int g_cur[MAXN];
__device__ int g_srcidx[MAXE];
__device__ int g_is64;                                   // edge_index dtype flag

// ---------------- 0) zero small scratch ---------------------------------------
__global__ void zero_kernel(int n) {
    int i      = blockIdx.x * blockDim.x + threadIdx.x;
    int stride = gridDim.x * blockDim.x;
    for (int k = i; k < n; k += stride) g_deg[k] = 0;
    if (i < 2 * D) g_colacc[i] = 0.0f;
    if (i == 0) g_is64 = 1;
}

// ---------------- 0b) detect edge_index dtype ---------------------------------
// int64 nonneg values < 2^31 have zero high words at every odd 32-bit position;
// int32 data has node indices there (P[all zero] ~ 0). Probe 4096 words.
__global__ void detect_kernel(const int* __restrict__ ei32, int n_words32) {
    int limit = min(n_words32, 4096);
    int nz = 0;
    for (int i = threadIdx.x * 2 + 1; i < limit; i += 512)
        nz |= (__ldg(ei32 + i) != 0);
    if (nz) g_is64 = 0;
}

// ---------------- index fetch helper -------------------------------------------
__device__ __forceinline__ int load_idx(const void* ei, int is64, int pos) {
    if (is64) return (int)__ldg((const long long*)ei + pos);
    return __ldg((const int*)ei + pos);
}

// ---------------- 1) count in-degrees (int atomics) ---------------------------
__global__ void count_kernel(const void* __restrict__ ei, int E, int N) {
    int i      = blockIdx.x * blockDim.x + threadIdx.x;
    int stride = gridDim.x * blockDim.x;
    int is64   = g_is64;
    for (int e = i; e < E; e += stride) {
        int d = load_idx(ei, is64, E + e);
        if ((unsigned)d < (unsigned)N) atomicAdd(&g_deg[d], 1);
    }
}

// ---------------- 2) exclusive prefix scan (1 block, 1024 threads) ------------
__global__ void scan_kernel(int n) {
    __shared__ int wsum[32];
    __shared__ int s_carry;
    int tid = threadIdx.x, lane = tid & 31, wid = tid >> 5;
    if (tid == 0) s_carry = 0;
    __syncthreads();
    for (int base = 0; base < n; base += 1024) {
        int i = base + tid;
        int v = (i < n) ? g_deg[i] : 0;
        int s = v;
#pragma unroll
        for (int o = 1; o < 32; o <<= 1) {
            int t = __shfl_up_sync(0xffffffffu, s, o);
            if (lane >= o) s += t;
        }
        if (lane == 31) wsum[wid] = s;
        __syncthreads();
        if (wid == 0) {
            int ws = wsum[lane];
#pragma unroll
            for (int o = 1; o < 32; o <<= 1) {
                int t = __shfl_up_sync(0xffffffffu, ws, o);
                if (lane >= o) ws += t;
            }
            wsum[lane] = ws;
        }
        __syncthreads();
        int incl = s + (wid > 0 ? wsum[wid - 1] : 0) + s_carry;
        int excl = incl - v;
        if (i < n) { g_off[i] = excl; g_cur[i] = excl; }
        __syncthreads();                    // all reads of old s_carry done
        if (tid == 1023) s_carry = incl;
        __syncthreads();
    }
    if (tid == 0) g_off[n] = s_carry;
}

// ---------------- 3) fill CSR buckets (int atomics on cursors) ----------------
__global__ void fill_kernel(const void* __restrict__ ei, int E, int N) {
    int i      = blockIdx.x * blockDim.x + threadIdx.x;
    int stride = gridDim.x * blockDim.x;
    int is64   = g_is64;
    for (int e = i; e < E; e += stride) {
        int s = load_idx(ei, is64, e);
        int d = load_idx(ei, is64, E + e);
        if ((unsigned)d < (unsigned)N) {
            int pos = atomicAdd(&g_cur[d], 1);
            if ((unsigned)s >= (unsigned)N) s = 0;   // safety, never expected
            g_srcidx[pos] = s;
        }
    }
}

// ---------------- 4) gather + mean: one warp per node, zero atomics -----------
__global__ void gather_kernel(const float* __restrict__ x, int N) {
    int gw   = (blockIdx.x * blockDim.x + threadIdx.x) >> 5;
    int lane = threadIdx.x & 31;
    int nw   = (gridDim.x * blockDim.x) >> 5;
    for (int v = gw; v < N; v += nw) {
        int beg = g_off[v], end = g_off[v + 1];
        float4 acc = make_float4(0.f, 0.f, 0.f, 0.f);
        for (int j = beg; j < end; j += 32) {
            int idx = (j + lane < end) ? __ldg(g_srcidx + j + lane) : 0;
            int m = min(32, end - j);
            for (int t = 0; t < m; t++) {
                int s = __shfl_sync(0xffffffffu, idx, t);
                float4 xv = __ldg((const float4*)(x + (size_t)s * D) + lane);
                acc.x += xv.x; acc.y += xv.y; acc.z += xv.z; acc.w += xv.w;
            }
        }
        float inv = 1.0f / fmaxf((float)(end - beg), 1.0f);
        acc.x *= inv; acc.y *= inv; acc.z *= inv; acc.w *= inv;
        ((float4*)(g_agg + (size_t)v * D))[lane] = acc;
    }
}

// ---------------- 5) fused GEMM: h = [agg | x] @ [Wl | Wr]^T + b --------------
// 64 rows x 128 cols per block, 256 threads, K=256 in 8 chunks of 32.
// Static shared (~26 KB). Thread (jt=tid&15, rt=tid>>4) owns 4 rows x 8 cols.
// BN column stats fused into the epilogue.
__global__ void __launch_bounds__(256) gemm_kernel(
    const float* __restrict__ x,  const float* __restrict__ Wl,
    const float* __restrict__ bl, const float* __restrict__ Wr, int N)
{
    __shared__ __align__(16) float u_s[KC][68];   // [k][row]
    __shared__ float w_s[128][33];                // [j][k]
    __shared__ float scol[2 * D];                 // sum | sumsq

    int tid  = threadIdx.x;
    int row0 = blockIdx.x * BM;
    int jt   = tid & 15;    // column group: cols jt + 16*c
    int rt   = tid >> 4;    // row group:    rows 4*rt .. 4*rt+3

    if (tid < 2 * D) scol[tid] = 0.0f;

    float acc[4][8];
#pragma unroll
    for (int i = 0; i < 4; i++)
#pragma unroll
        for (int c = 0; c < 8; c++) acc[i][c] = 0.0f;

    for (int kc = 0; kc < 256 / KC; kc++) {
        int k0 = kc * KC;
        const float* Wsrc = (k0 < 128) ? Wl : Wr;
        const float* Usrc = (k0 < 128) ? g_agg : x;
        int kk = (k0 < 128) ? k0 : (k0 - 128);

        __syncthreads();   // previous chunk fully consumed
        for (int idx = tid; idx < 128 * KC; idx += 256) {
            int j = idx >> 5, k = idx & 31;
            w_s[j][k] = __ldg(Wsrc + j * D + kk + k);
        }
        for (int idx = tid; idx < BM * KC; idx += 256) {
            int row = idx >> 5, k = idx & 31;
            int gr = row0 + row;
            float v = (gr < N) ? __ldg(Usrc + (size_t)gr * D + kk + k) : 0.0f;
            u_s[k][row] = v;
        }
        __syncthreads();

#pragma unroll
        for (int k = 0; k < KC; k++) {
            float4 u4 = *(const float4*)&u_s[k][rt * 4];
            float wv[8];
#pragma unroll
            for (int c = 0; c < 8; c++) wv[c] = w_s[jt + 16 * c][k];
#pragma unroll
            for (int c = 0; c < 8; c++) {
                acc[0][c] = fmaf(u4.x, wv[c], acc[0][c]);
                acc[1][c] = fmaf(u4.y, wv[c], acc[1][c]);
                acc[2][c] = fmaf(u4.z, wv[c], acc[2][c]);
                acc[3][c] = fmaf(u4.w, wv[c], acc[3][c]);
            }
        }
    }

    // epilogue: + bias, store h, per-column BN partials
#pragma unroll
    for (int c = 0; c < 8; c++) {
        int j = jt + 16 * c;
        float bj = __ldg(bl + j);
        float s = 0.0f, sq = 0.0f;
#pragma unroll
        for (int i = 0; i < 4; i++) {
            int row = row0 + rt * 4 + i;
            if (row < N) {
                float v = acc[i][c] + bj;
                g_h[(size_t)row * D + j] = v;
                s += v; sq += v * v;
            }
        }
        atomicAdd(&scol[j], s);
        atomicAdd(&scol[D + j], sq);
    }
    __syncthreads();
    if (tid < 2 * D) atomicAdd(&g_colacc[tid], scol[tid]);
}

// ---------------- 6) BN parameter finalize (1 block, 128 threads) -------------
__global__ void bnfin_kernel(const float* __restrict__ gamma,
                             const float* __restrict__ beta, float invN) {
    int j = threadIdx.x;
    float mu  = g_colacc[j] * invN;
    float var = g_colacc[D + j] * invN - mu * mu;
    float rs  = rsqrtf(var + 1e-5f);
    float a   = gamma[j] * rs;
    g_ab[j]     = a;
    g_ab[D + j] = beta[j] - mu * a;
}

// ---------------- 7) out = relu(h*a + b + x), float4 vectorized ---------------
__global__ void finalize_kernel(const float* __restrict__ x,
                                float* __restrict__ out, int N) {
    int idx   = blockIdx.x * blockDim.x + threadIdx.x;
    int total = N * (D / 4);
    if (idx >= total) return;
    int c4 = idx & 31;
    float4 h  = ((const float4*)g_h)[idx];
    float4 xv = __ldg((const float4*)x + idx);
    const float4* a4 = (const float4*)g_ab;
    float4 a = a4[c4];
    float4 b = a4[32 + c4];
    float4 o;
    o.x = fmaxf(fmaf(h.x, a.x, b.x) + xv.x, 0.0f);
    o.y = fmaxf(fmaf(h.y, a.y, b.y) + xv.y, 0.0f);
    o.z = fmaxf(fmaf(h.z, a.z, b.z) + xv.z, 0.0f);
    o.w = fmaxf(fmaf(h.w, a.w, b.w) + xv.w, 0.0f);
    ((float4*)out)[idx] = o;
}

// ------------------------------------------------------------------------------
extern "C" void kernel_launch(void* const* d_in, const int* in_sizes, int n_in,
                              void* d_out, int out_size) {
    const float* x     = (const float*)d_in[0];
    const void*  ei    = d_in[1];                 // int32 OR int64, detected on device
    const float* Wl    = (const float*)d_in[2];
    const float* bl    = (const float*)d_in[3];
    const float* Wr    = (const float*)d_in[4];
    const float* gamma = (const float*)d_in[5];
    const float* beta  = (const float*)d_in[6];
    int N = in_sizes[0] / D;
    int E = in_sizes[1] / 2;

    zero_kernel<<<148, 256>>>(N);
    detect_kernel<<<1, 256>>>((const int*)ei, 2 * E);
    count_kernel<<<1184, 256>>>(ei, E, N);
    scan_kernel<<<1, 1024>>>(N);
    fill_kernel<<<1184, 256>>>(ei, E, N);
    gather_kernel<<<1184, 256>>>(x, N);

    gemm_kernel<<<(N + BM - 1) / BM, 256>>>(x, Wl, bl, Wr, N);

    bnfin_kernel<<<1, 128>>>(gamma, beta, 1.0f / (float)N);

    int total4 = N * (D / 4);
    finalize_kernel<<<(total4 + 255) / 256, 256>>>(x, (float*)d_out, N);
}

// round 12
// speedup vs baseline: 1.1916x; 1.1916x over previous
#include <cuda_runtime.h>
#include <math.h>

#define D 128
#define MAXN 100000
#define MAXE 1600000
#define BM 64
#define KC 32

// ---------------- scratch (static device globals; 16B-aligned for float4) -----
__device__ __align__(16) float g_agg[(size_t)MAXN * D];  // aggregated MEAN feats
__device__ __align__(16) float g_h[(size_t)MAXN * D];    // pre-BN hidden
__device__ __align__(16) float g_colacc[2 * D];          // col sum | col sumsq
__device__ __align__(16) float g_ab[2 * D];              // bn scale | bn shift
__device__ int g_deg[MAXN];
__device__ int g_off[MAXN + 1];
__device__ int g_cur[MAXN];
__device__ int g_srcidx[MAXE];
__device__ int g_bsum[128];                              // per-block scan sums
__device__ int g_is64;                                   // edge_index dtype flag

// ---------------- 0) zero small scratch ---------------------------------------
__global__ void zero_kernel(int n) {
    int i      = blockIdx.x * blockDim.x + threadIdx.x;
    int stride = gridDim.x * blockDim.x;
    for (int k = i; k < n; k += stride) g_deg[k] = 0;
    if (i < 2 * D) g_colacc[i] = 0.0f;
    if (i == 0) g_is64 = 1;
}

// ---------------- 0b) detect edge_index dtype ---------------------------------
// int64 nonneg values < 2^31 have zero high words at every odd 32-bit position;
// int32 data has node indices there (P[all zero] ~ 0). Probe 4096 words.
__global__ void detect_kernel(const int* __restrict__ ei32, int n_words32) {
    int limit = min(n_words32, 4096);
    int nz = 0;
    for (int i = threadIdx.x * 2 + 1; i < limit; i += 512)
        nz |= (__ldg(ei32 + i) != 0);
    if (nz) g_is64 = 0;
}

// ---------------- index fetch helper -------------------------------------------
__device__ __forceinline__ int load_idx(const void* ei, int is64, int pos) {
    if (is64) return (int)__ldg((const long long*)ei + pos);
    return __ldg((const int*)ei + pos);
}

// ---------------- 1) count in-degrees (int atomics) ---------------------------
__global__ void count_kernel(const void* __restrict__ ei, int E, int N) {
    int i      = blockIdx.x * blockDim.x + threadIdx.x;
    int stride = gridDim.x * blockDim.x;
    int is64   = g_is64;
    for (int e = i; e < E; e += stride) {
        int d = load_idx(ei, is64, E + e);
        if ((unsigned)d < (unsigned)N) atomicAdd(&g_deg[d], 1);
    }
}

// ---------------- 2) two-level exclusive scan (full-grid, ~8us total) ---------
// scanA: per-block exclusive scan of 1024 elements + block total
__global__ void scanA_kernel(int n) {
    __shared__ int wsum[32];
    int tid = threadIdx.x, lane = tid & 31, wid = tid >> 5;
    int i = blockIdx.x * 1024 + tid;
    int v = (i < n) ? g_deg[i] : 0;
    int s = v;
#pragma unroll
    for (int o = 1; o < 32; o <<= 1) {
        int t = __shfl_up_sync(0xffffffffu, s, o);
        if (lane >= o) s += t;
    }
    if (lane == 31) wsum[wid] = s;
    __syncthreads();
    if (wid == 0) {
        int ws = wsum[lane];
#pragma unroll
        for (int o = 1; o < 32; o <<= 1) {
            int t = __shfl_up_sync(0xffffffffu, ws, o);
            if (lane >= o) ws += t;
        }
        wsum[lane] = ws;
    }
    __syncthreads();
    int incl = s + (wid > 0 ? wsum[wid - 1] : 0);
    if (i < n) g_off[i] = incl - v;           // block-local exclusive
    if (tid == 1023) g_bsum[blockIdx.x] = incl;  // block total
}

// scanB: exclusive scan of <=128 block sums (1 block); writes grand total
__global__ void scanB_kernel(int nb, int n) {
    __shared__ int wsum[4];
    int tid = threadIdx.x, lane = tid & 31, wid = tid >> 5;
    int v = (tid < nb) ? g_bsum[tid] : 0;
    int s = v;
#pragma unroll
    for (int o = 1; o < 32; o <<= 1) {
        int t = __shfl_up_sync(0xffffffffu, s, o);
        if (lane >= o) s += t;
    }
    if (lane == 31) wsum[wid] = s;
    __syncthreads();
    int base = 0;
    for (int w = 0; w < wid; w++) base += wsum[w];
    int incl = s + base;
    if (tid < nb) g_bsum[tid] = incl - v;     // exclusive
    if (tid == 127) g_off[n] = incl;          // grand total
}

// scanC: add block offsets; materialize g_off and g_cur
__global__ void scanC_kernel(int n) {
    int i = blockIdx.x * 1024 + threadIdx.x;
    if (i < n) {
        int o = g_off[i] + g_bsum[blockIdx.x];
        g_off[i] = o;
        g_cur[i] = o;
    }
}

// ---------------- 3) fill CSR buckets (int atomics on cursors) ----------------
__global__ void fill_kernel(const void* __restrict__ ei, int E, int N) {
    int i      = blockIdx.x * blockDim.x + threadIdx.x;
    int stride = gridDim.x * blockDim.x;
    int is64   = g_is64;
    for (int e = i; e < E; e += stride) {
        int s = load_idx(ei, is64, e);
        int d = load_idx(ei, is64, E + e);
        if ((unsigned)d < (unsigned)N) {
            int pos = atomicAdd(&g_cur[d], 1);
            if ((unsigned)s >= (unsigned)N) s = 0;   // safety, never expected
            g_srcidx[pos] = s;
        }
    }
}

// ---------------- 4) gather + mean: one warp per node, zero atomics -----------
__global__ void gather_kernel(const float* __restrict__ x, int N) {
    int gw   = (blockIdx.x * blockDim.x + threadIdx.x) >> 5;
    int lane = threadIdx.x & 31;
    int nw   = (gridDim.x * blockDim.x) >> 5;
    for (int v = gw; v < N; v += nw) {
        int beg = g_off[v], end = g_off[v + 1];
        float4 acc = make_float4(0.f, 0.f, 0.f, 0.f);
        for (int j = beg; j < end; j += 32) {
            int idx = (j + lane < end) ? __ldg(g_srcidx + j + lane) : 0;
            int m = min(32, end - j);
            for (int t = 0; t < m; t++) {
                int s = __shfl_sync(0xffffffffu, idx, t);
                float4 xv = __ldg((const float4*)(x + (size_t)s * D) + lane);
                acc.x += xv.x; acc.y += xv.y; acc.z += xv.z; acc.w += xv.w;
            }
        }
        float inv = 1.0f / fmaxf((float)(end - beg), 1.0f);
        acc.x *= inv; acc.y *= inv; acc.z *= inv; acc.w *= inv;
        ((float4*)(g_agg + (size_t)v * D))[lane] = acc;
    }
}

// ---------------- 5) fused GEMM: h = [agg | x] @ [Wl | Wr]^T + b --------------
// 64 rows x 128 cols per block, 256 threads, K=256 in 8 chunks of 32.
// Static shared (~26 KB). Thread (jt=tid&15, rt=tid>>4) owns 4 rows x 8 cols.
// BN column stats fused into the epilogue.
__global__ void __launch_bounds__(256) gemm_kernel(
    const float* __restrict__ x,  const float* __restrict__ Wl,
    const float* __restrict__ bl, const float* __restrict__ Wr, int N)
{
    __shared__ __align__(16) float u_s[KC][68];   // [k][row]
    __shared__ float w_s[128][33];                // [j][k]
    __shared__ float scol[2 * D];                 // sum | sumsq

    int tid  = threadIdx.x;
    int row0 = blockIdx.x * BM;
    int jt   = tid & 15;    // column group: cols jt + 16*c
    int rt   = tid >> 4;    // row group:    rows 4*rt .. 4*rt+3

    if (tid < 2 * D) scol[tid] = 0.0f;

    float acc[4][8];
#pragma unroll
    for (int i = 0; i < 4; i++)
#pragma unroll
        for (int c = 0; c < 8; c++) acc[i][c] = 0.0f;

    for (int kc = 0; kc < 256 / KC; kc++) {
        int k0 = kc * KC;
        const float* Wsrc = (k0 < 128) ? Wl : Wr;
        const float* Usrc = (k0 < 128) ? g_agg : x;
        int kk = (k0 < 128) ? k0 : (k0 - 128);

        __syncthreads();   // previous chunk fully consumed
        for (int idx = tid; idx < 128 * KC; idx += 256) {
            int j = idx >> 5, k = idx & 31;
            w_s[j][k] = __ldg(Wsrc + j * D + kk + k);
        }
        for (int idx = tid; idx < BM * KC; idx += 256) {
            int row = idx >> 5, k = idx & 31;
            int gr = row0 + row;
            float v = (gr < N) ? __ldg(Usrc + (size_t)gr * D + kk + k) : 0.0f;
            u_s[k][row] = v;
        }
        __syncthreads();

#pragma unroll
        for (int k = 0; k < KC; k++) {
            float4 u4 = *(const float4*)&u_s[k][rt * 4];
            float wv[8];
#pragma unroll
            for (int c = 0; c < 8; c++) wv[c] = w_s[jt + 16 * c][k];
#pragma unroll
            for (int c = 0; c < 8; c++) {
                acc[0][c] = fmaf(u4.x, wv[c], acc[0][c]);
                acc[1][c] = fmaf(u4.y, wv[c], acc[1][c]);
                acc[2][c] = fmaf(u4.z, wv[c], acc[2][c]);
                acc[3][c] = fmaf(u4.w, wv[c], acc[3][c]);
            }
        }
    }

    // epilogue: + bias, store h, per-column BN partials
#pragma unroll
    for (int c = 0; c < 8; c++) {
        int j = jt + 16 * c;
        float bj = __ldg(bl + j);
        float s = 0.0f, sq = 0.0f;
#pragma unroll
        for (int i = 0; i < 4; i++) {
            int row = row0 + rt * 4 + i;
            if (row < N) {
                float v = acc[i][c] + bj;
                g_h[(size_t)row * D + j] = v;
                s += v; sq += v * v;
            }
        }
        atomicAdd(&scol[j], s);
        atomicAdd(&scol[D + j], sq);
    }
    __syncthreads();
    if (tid < 2 * D) atomicAdd(&g_colacc[tid], scol[tid]);
}

// ---------------- 6) BN parameter finalize (1 block, 128 threads) -------------
__global__ void bnfin_kernel(const float* __restrict__ gamma,
                             const float* __restrict__ beta, float invN) {
    int j = threadIdx.x;
    float mu  = g_colacc[j] * invN;
    float var = g_colacc[D + j] * invN - mu * mu;
    float rs  = rsqrtf(var + 1e-5f);
    float a   = gamma[j] * rs;
    g_ab[j]     = a;
    g_ab[D + j] = beta[j] - mu * a;
}

// ---------------- 7) out = relu(h*a + b + x), float4 vectorized ---------------
__global__ void finalize_kernel(const float* __restrict__ x,
                                float* __restrict__ out, int N) {
    int idx   = blockIdx.x * blockDim.x + threadIdx.x;
    int total = N * (D / 4);
    if (idx >= total) return;
    int c4 = idx & 31;
    float4 h  = ((const float4*)g_h)[idx];
    float4 xv = __ldg((const float4*)x + idx);
    const float4* a4 = (const float4*)g_ab;
    float4 a = a4[c4];
    float4 b = a4[32 + c4];
    float4 o;
    o.x = fmaxf(fmaf(h.x, a.x, b.x) + xv.x, 0.0f);
    o.y = fmaxf(fmaf(h.y, a.y, b.y) + xv.y, 0.0f);
    o.z = fmaxf(fmaf(h.z, a.z, b.z) + xv.z, 0.0f);
    o.w = fmaxf(fmaf(h.w, a.w, b.w) + xv.w, 0.0f);
    ((float4*)out)[idx] = o;
}

// ------------------------------------------------------------------------------
extern "C" void kernel_launch(void* const* d_in, const int* in_sizes, int n_in,
                              void* d_out, int out_size) {
    const float* x     = (const float*)d_in[0];
    const void*  ei    = d_in[1];                 // int32 OR int64, detected on device
    const float* Wl    = (const float*)d_in[2];
    const float* bl    = (const float*)d_in[3];
    const float* Wr    = (const float*)d_in[4];
    const float* gamma = (const float*)d_in[5];
    const float* beta  = (const float*)d_in[6];
    int N = in_sizes[0] / D;
    int E = in_sizes[1] / 2;

    zero_kernel<<<148, 256>>>(N);
    detect_kernel<<<1, 256>>>((const int*)ei, 2 * E);
    count_kernel<<<1184, 256>>>(ei, E, N);

    int nb = (N + 1023) / 1024;   // <=128 for MAXN=100000 (needs N<=131072)
    scanA_kernel<<<nb, 1024>>>(N);
    scanB_kernel<<<1, 128>>>(nb, N);
    scanC_kernel<<<nb, 1024>>>(N);

    fill_kernel<<<1184, 256>>>(ei, E, N);
    gather_kernel<<<1184, 256>>>(x, N);

    gemm_kernel<<<(N + BM - 1) / BM, 256>>>(x, Wl, bl, Wr, N);

    bnfin_kernel<<<1, 128>>>(gamma, beta, 1.0f / (float)N);

    int total4 = N * (D / 4);
    finalize_kernel<<<(total4 + 255) / 256, 256>>>(x, (float*)d_out, N);
}

// round 13
// speedup vs baseline: 1.2283x; 1.0308x over previous
#include <cuda_runtime.h>
#include <math.h>

#define D 128
#define MAXN 100000
#define MAXE 1600000
#define BM 64
#define KC 32

// ---------------- scratch (static device globals; 16B-aligned for float4) -----
__device__ __align__(16) float g_agg[(size_t)MAXN * D];  // aggregated MEAN feats
__device__ __align__(16) float g_h[(size_t)MAXN * D];    // pre-BN hidden
__device__ __align__(16) float g_colacc[2 * D];          // col sum | col sumsq
__device__ __align__(16) float g_ab[2 * D];              // bn scale | bn shift
__device__ int g_deg[MAXN];
__device__ int g_off[MAXN + 1];
__device__ int g_cur[MAXN];
__device__ int g_srcidx[MAXE];
__device__ int g_bsum[128];                              // per-block scan sums
__device__ int g_is64;                                   // edge_index dtype flag

// ---------------- f32x2 packed-math helpers (Blackwell FFMA2) -----------------
__device__ __forceinline__ unsigned long long pk2(float lo, float hi) {
    unsigned long long r;
    asm("mov.b64 %0, {%1, %2};" : "=l"(r) : "f"(lo), "f"(hi));
    return r;
}
__device__ __forceinline__ void upk2(unsigned long long v, float& lo, float& hi) {
    asm("mov.b64 {%0, %1}, %2;" : "=f"(lo), "=f"(hi) : "l"(v));
}
__device__ __forceinline__ void fma2(unsigned long long& a, unsigned long long u,
                                     unsigned long long w) {
    asm("fma.rn.f32x2 %0, %1, %2, %0;" : "+l"(a) : "l"(u), "l"(w));
}

// ---------------- 0) zero small scratch ---------------------------------------
__global__ void zero_kernel(int n) {
    int i      = blockIdx.x * blockDim.x + threadIdx.x;
    int stride = gridDim.x * blockDim.x;
    for (int k = i; k < n; k += stride) g_deg[k] = 0;
    if (i < 2 * D) g_colacc[i] = 0.0f;
    if (i == 0) g_is64 = 1;
}

// ---------------- 0b) detect edge_index dtype ---------------------------------
__global__ void detect_kernel(const int* __restrict__ ei32, int n_words32) {
    int limit = min(n_words32, 4096);
    int nz = 0;
    for (int i = threadIdx.x * 2 + 1; i < limit; i += 512)
        nz |= (__ldg(ei32 + i) != 0);
    if (nz) g_is64 = 0;
}

// ---------------- index fetch helper -------------------------------------------
__device__ __forceinline__ int load_idx(const void* ei, int is64, int pos) {
    if (is64) return (int)__ldg((const long long*)ei + pos);
    return __ldg((const int*)ei + pos);
}

// ---------------- 1) count in-degrees (int atomics) ---------------------------
__global__ void count_kernel(const void* __restrict__ ei, int E, int N) {
    int i      = blockIdx.x * blockDim.x + threadIdx.x;
    int stride = gridDim.x * blockDim.x;
    int is64   = g_is64;
    for (int e = i; e < E; e += stride) {
        int d = load_idx(ei, is64, E + e);
        if ((unsigned)d < (unsigned)N) atomicAdd(&g_deg[d], 1);
    }
}

// ---------------- 2) two-level exclusive scan (full-grid) ---------------------
__global__ void scanA_kernel(int n) {
    __shared__ int wsum[32];
    int tid = threadIdx.x, lane = tid & 31, wid = tid >> 5;
    int i = blockIdx.x * 1024 + tid;
    int v = (i < n) ? g_deg[i] : 0;
    int s = v;
#pragma unroll
    for (int o = 1; o < 32; o <<= 1) {
        int t = __shfl_up_sync(0xffffffffu, s, o);
        if (lane >= o) s += t;
    }
    if (lane == 31) wsum[wid] = s;
    __syncthreads();
    if (wid == 0) {
        int ws = wsum[lane];
#pragma unroll
        for (int o = 1; o < 32; o <<= 1) {
            int t = __shfl_up_sync(0xffffffffu, ws, o);
            if (lane >= o) ws += t;
        }
        wsum[lane] = ws;
    }
    __syncthreads();
    int incl = s + (wid > 0 ? wsum[wid - 1] : 0);
    if (i < n) g_off[i] = incl - v;
    if (tid == 1023) g_bsum[blockIdx.x] = incl;
}

__global__ void scanB_kernel(int nb, int n) {
    __shared__ int wsum[4];
    int tid = threadIdx.x, lane = tid & 31, wid = tid >> 5;
    int v = (tid < nb) ? g_bsum[tid] : 0;
    int s = v;
#pragma unroll
    for (int o = 1; o < 32; o <<= 1) {
        int t = __shfl_up_sync(0xffffffffu, s, o);
        if (lane >= o) s += t;
    }
    if (lane == 31) wsum[wid] = s;
    __syncthreads();
    int base = 0;
    for (int w = 0; w < wid; w++) base += wsum[w];
    int incl = s + base;
    if (tid < nb) g_bsum[tid] = incl - v;
    if (tid == 127) g_off[n] = incl;
}

__global__ void scanC_kernel(int n) {
    int i = blockIdx.x * 1024 + threadIdx.x;
    if (i < n) {
        int o = g_off[i] + g_bsum[blockIdx.x];
        g_off[i] = o;
        g_cur[i] = o;
    }
}

// ---------------- 3) fill CSR buckets (int atomics on cursors) ----------------
__global__ void fill_kernel(const void* __restrict__ ei, int E, int N) {
    int i      = blockIdx.x * blockDim.x + threadIdx.x;
    int stride = gridDim.x * blockDim.x;
    int is64   = g_is64;
    for (int e = i; e < E; e += stride) {
        int s = load_idx(ei, is64, e);
        int d = load_idx(ei, is64, E + e);
        if ((unsigned)d < (unsigned)N) {
            int pos = atomicAdd(&g_cur[d], 1);
            if ((unsigned)s >= (unsigned)N) s = 0;   // safety, never expected
            g_srcidx[pos] = s;
        }
    }
}

// ---------------- 4) gather + mean: one warp per node, zero atomics -----------
__global__ void gather_kernel(const float* __restrict__ x, int N) {
    int gw   = (blockIdx.x * blockDim.x + threadIdx.x) >> 5;
    int lane = threadIdx.x & 31;
    int nw   = (gridDim.x * blockDim.x) >> 5;
    for (int v = gw; v < N; v += nw) {
        int beg = g_off[v], end = g_off[v + 1];
        float4 acc = make_float4(0.f, 0.f, 0.f, 0.f);
        for (int j = beg; j < end; j += 32) {
            int idx = (j + lane < end) ? __ldg(g_srcidx + j + lane) : 0;
            int m = min(32, end - j);
            for (int t = 0; t < m; t++) {
                int s = __shfl_sync(0xffffffffu, idx, t);
                float4 xv = __ldg((const float4*)(x + (size_t)s * D) + lane);
                acc.x += xv.x; acc.y += xv.y; acc.z += xv.z; acc.w += xv.w;
            }
        }
        float inv = 1.0f / fmaxf((float)(end - beg), 1.0f);
        acc.x *= inv; acc.y *= inv; acc.z *= inv; acc.w *= inv;
        ((float4*)(g_agg + (size_t)v * D))[lane] = acc;
    }
}

// ---------------- 5) fused GEMM: h = [agg | x] @ [Wl | Wr]^T + b --------------
// Same tile/thread mapping as the passing r12 kernel; inner loop converted to
// packed fma.rn.f32x2 (row-pairs share the broadcast W operand): 32 FFMA ->
// 16 FFMA2 per k-step per thread. BN column stats fused into the epilogue.
__global__ void __launch_bounds__(256) gemm_kernel(
    const float* __restrict__ x,  const float* __restrict__ Wl,
    const float* __restrict__ bl, const float* __restrict__ Wr, int N)
{
    __shared__ __align__(16) float u_s[KC][68];   // [k][row]
    __shared__ float w_s[128][33];                // [j][k]
    __shared__ float scol[2 * D];                 // sum | sumsq

    int tid  = threadIdx.x;
    int row0 = blockIdx.x * BM;
    int jt   = tid & 15;    // column group: cols jt + 16*c
    int rt   = tid >> 4;    // row group:    rows 4*rt .. 4*rt+3

    if (tid < 2 * D) scol[tid] = 0.0f;

    unsigned long long acc2[2][8];   // [row-pair][col]; pair0=rows(0,1), pair1=(2,3)
#pragma unroll
    for (int p = 0; p < 2; p++)
#pragma unroll
        for (int c = 0; c < 8; c++) acc2[p][c] = 0ull;

    for (int kc = 0; kc < 256 / KC; kc++) {
        int k0 = kc * KC;
        const float* Wsrc = (k0 < 128) ? Wl : Wr;
        const float* Usrc = (k0 < 128) ? g_agg : x;
        int kk = (k0 < 128) ? k0 : (k0 - 128);

        __syncthreads();   // previous chunk fully consumed
        for (int idx = tid; idx < 128 * KC; idx += 256) {
            int j = idx >> 5, k = idx & 31;
            w_s[j][k] = __ldg(Wsrc + j * D + kk + k);
        }
        for (int idx = tid; idx < BM * KC; idx += 256) {
            int row = idx >> 5, k = idx & 31;
            int gr = row0 + row;
            float v = (gr < N) ? __ldg(Usrc + (size_t)gr * D + kk + k) : 0.0f;
            u_s[k][row] = v;
        }
        __syncthreads();

#pragma unroll
        for (int k = 0; k < KC; k++) {
            float4 u4 = *(const float4*)&u_s[k][rt * 4];
            unsigned long long ua = pk2(u4.x, u4.y);
            unsigned long long ub = pk2(u4.z, u4.w);
#pragma unroll
            for (int c = 0; c < 8; c++) {
                float w = w_s[jt + 16 * c][k];
                unsigned long long w2 = pk2(w, w);
                fma2(acc2[0][c], ua, w2);
                fma2(acc2[1][c], ub, w2);
            }
        }
    }

    // epilogue: + bias, store h, per-column BN partials
#pragma unroll
    for (int c = 0; c < 8; c++) {
        int j = jt + 16 * c;
        float bj = __ldg(bl + j);
        float s = 0.0f, sq = 0.0f;
        float v[4];
        upk2(acc2[0][c], v[0], v[1]);
        upk2(acc2[1][c], v[2], v[3]);
#pragma unroll
        for (int i = 0; i < 4; i++) {
            int row = row0 + rt * 4 + i;
            if (row < N) {
                float h = v[i] + bj;
                g_h[(size_t)row * D + j] = h;
                s += h; sq += h * h;
            }
        }
        atomicAdd(&scol[j], s);
        atomicAdd(&scol[D + j], sq);
    }
    __syncthreads();
    if (tid < 2 * D) atomicAdd(&g_colacc[tid], scol[tid]);
}

// ---------------- 6) BN parameter finalize (1 block, 128 threads) -------------
__global__ void bnfin_kernel(const float* __restrict__ gamma,
                             const float* __restrict__ beta, float invN) {
    int j = threadIdx.x;
    float mu  = g_colacc[j] * invN;
    float var = g_colacc[D + j] * invN - mu * mu;
    float rs  = rsqrtf(var + 1e-5f);
    float a   = gamma[j] * rs;
    g_ab[j]     = a;
    g_ab[D + j] = beta[j] - mu * a;
}

// ---------------- 7) out = relu(h*a + b + x), float4 vectorized ---------------
__global__ void finalize_kernel(const float* __restrict__ x,
                                float* __restrict__ out, int N) {
    int idx   = blockIdx.x * blockDim.x + threadIdx.x;
    int total = N * (D / 4);
    if (idx >= total) return;
    int c4 = idx & 31;
    float4 h  = ((const float4*)g_h)[idx];
    float4 xv = __ldg((const float4*)x + idx);
    const float4* a4 = (const float4*)g_ab;
    float4 a = a4[c4];
    float4 b = a4[32 + c4];
    float4 o;
    o.x = fmaxf(fmaf(h.x, a.x, b.x) + xv.x, 0.0f);
    o.y = fmaxf(fmaf(h.y, a.y, b.y) + xv.y, 0.0f);
    o.z = fmaxf(fmaf(h.z, a.z, b.z) + xv.z, 0.0f);
    o.w = fmaxf(fmaf(h.w, a.w, b.w) + xv.w, 0.0f);
    ((float4*)out)[idx] = o;
}

// ------------------------------------------------------------------------------
extern "C" void kernel_launch(void* const* d_in, const int* in_sizes, int n_in,
                              void* d_out, int out_size) {
    const float* x     = (const float*)d_in[0];
    const void*  ei    = d_in[1];                 // int32 OR int64, detected on device
    const float* Wl    = (const float*)d_in[2];
    const float* bl    = (const float*)d_in[3];
    const float* Wr    = (const float*)d_in[4];
    const float* gamma = (const float*)d_in[5];
    const float* beta  = (const float*)d_in[6];
    int N = in_sizes[0] / D;
    int E = in_sizes[1] / 2;

    zero_kernel<<<148, 256>>>(N);
    detect_kernel<<<1, 256>>>((const int*)ei, 2 * E);
    count_kernel<<<1184, 256>>>(ei, E, N);

    int nb = (N + 1023) / 1024;   // <=128 for MAXN=100000
    scanA_kernel<<<nb, 1024>>>(N);
    scanB_kernel<<<1, 128>>>(nb, N);
    scanC_kernel<<<nb, 1024>>>(N);

    fill_kernel<<<1184, 256>>>(ei, E, N);
    gather_kernel<<<1184, 256>>>(x, N);

    gemm_kernel<<<(N + BM - 1) / BM, 256>>>(x, Wl, bl, Wr, N);

    bnfin_kernel<<<1, 128>>>(gamma, beta, 1.0f / (float)N);

    int total4 = N * (D / 4);
    finalize_kernel<<<(total4 + 255) / 256, 256>>>(x, (float*)d_out, N);
}